// round 1
// baseline (speedup 1.0000x reference)
#include <cuda_runtime.h>
#include <cstdint>

// Problem constants (fixed shapes per reference)
#define BB   8
#define HH   512
#define WW   512
#define HWPX (HH * WW)          // 262144 pixels per batch
#define CC   64                 // channels
#define SS   256                // superpixels per batch

// Grid sizing: 3 CTAs/SM * 148 SMs = 444 slots. 55*8 = 440 blocks -> single wave.
#define NBLK_PER_B 55
#define CHUNK ((HWPX + NBLK_PER_B - 1) / NBLK_PER_B)   // 4767
#define UNROLL 32

// SMEM: 256*64 float sums (64 KB) + 256 int counts (1 KB)
#define SMEM_BYTES (SS * CC * sizeof(float) + SS * sizeof(int))

// Global scratch (no allocations allowed -> __device__ globals)
__device__ float g_sums[BB * SS * CC];
__device__ float g_counts[BB * SS];

__global__ void zero_kernel() {
    int i = blockIdx.x * blockDim.x + threadIdx.x;
    if (i < BB * SS * CC) g_sums[i] = 0.0f;
    if (i < BB * SS)      g_counts[i] = 0.0f;
}

__global__ void __launch_bounds__(64, 3)
pool_kernel(const float* __restrict__ feat, const int* __restrict__ lab) {
    extern __shared__ float smem[];
    float* ssum = smem;                       // [SS * CC]
    int*   scnt = (int*)(smem + SS * CC);     // [SS]

    const int tid = threadIdx.x;              // 0..63 == channel id
    const int c   = tid;

    // Zero shared accumulators
    #pragma unroll 4
    for (int i = tid; i < SS * CC; i += 64) ssum[i] = 0.0f;
    for (int i = tid; i < SS;      i += 64) scnt[i] = 0;
    __syncthreads();

    const int b = blockIdx.y;
    const float* f = feat + (size_t)b * HWPX * CC;
    const int*   l = lab  + (size_t)b * HWPX;

    const int start = blockIdx.x * CHUNK;
    const int end   = min(start + CHUNK, HWPX);

    int p = start;
    // Main unrolled loop: whole block (both warps) cooperates on each pixel,
    // so the SMEM RMW below is race-free without atomics.
    for (; p + UNROLL <= end; p += UNROLL) {
        int   lbl[UNROLL];
        float v[UNROLL];
        #pragma unroll
        for (int u = 0; u < UNROLL; u++) {
            lbl[u] = __ldg(l + p + u);                       // broadcast load
            v[u]   = __ldg(f + (size_t)(p + u) * CC + c);    // coalesced 256B/pixel
        }
        #pragma unroll
        for (int u = 0; u < UNROLL; u++) {
            ssum[lbl[u] * CC + c] += v[u];                   // LDS+FADD+STS, conflict-free
        }
        // Counts: lanes 0..31 of warp0 each count one pixel of this group.
        // Reload label (L1 hit) to avoid dynamic register-array indexing.
        if (tid < UNROLL) atomicAdd(&scnt[__ldg(l + p + tid)], 1);
    }
    // Tail
    for (; p < end; p++) {
        int lb = l[p];
        ssum[lb * CC + c] += f[(size_t)p * CC + c];
        if (tid == 0) atomicAdd(&scnt[lb], 1);
    }
    __syncthreads();

    // Flush partials to global. Threads 0..63 cover one segment row per step:
    // 64 consecutive floats -> coalesced 256B RED.ADD bursts.
    float* gs = g_sums + (size_t)b * SS * CC;
    for (int s = 0; s < SS; s++) {
        if (scnt[s] != 0) {                      // uniform branch across block
            atomicAdd(&gs[s * CC + c], ssum[s * CC + c]);
        }
    }
    for (int s = tid; s < SS; s += 64) {
        int cnt = scnt[s];
        if (cnt != 0) atomicAdd(&g_counts[b * SS + s], (float)cnt);
    }
}

__global__ void mean_kernel(float* __restrict__ out) {
    int i = blockIdx.x * blockDim.x + threadIdx.x;
    if (i < BB * SS * CC) {
        int seg = i >> 6;   // / CC
        float cnt = g_counts[seg];
        out[i] = g_sums[i] / fmaxf(cnt, 1.0f);
    }
}

extern "C" void kernel_launch(void* const* d_in, const int* in_sizes, int n_in,
                              void* d_out, int out_size) {
    const float* feat = (const float*)d_in[0];
    const int*   lab  = (const int*)d_in[1];
    float*       out  = (float*)d_out;

    // Opt-in to >48KB dynamic SMEM (idempotent; host-side attr, not captured)
    cudaFuncSetAttribute(pool_kernel,
                         cudaFuncAttributeMaxDynamicSharedMemorySize,
                         (int)SMEM_BYTES);

    // 1) zero global scratch
    {
        int n = BB * SS * CC;   // covers counts range too (BB*SS < BB*SS*CC)
        zero_kernel<<<(n + 255) / 256, 256>>>();
    }
    // 2) main pooling pass
    {
        dim3 grid(NBLK_PER_B, BB);
        pool_kernel<<<grid, 64, SMEM_BYTES>>>(feat, lab);
    }
    // 3) finalize means
    {
        int n = BB * SS * CC;
        mean_kernel<<<(n + 255) / 256, 256>>>(out);
    }
}

// round 2
// speedup vs baseline: 1.7478x; 1.7478x over previous
#include <cuda_runtime.h>
#include <cstdint>

// Fixed problem shape
#define BB    8
#define HWPX  (512 * 512)      // pixels per batch
#define CC    64               // channels
#define SS    256              // superpixels per batch

// Decomposition
#define NBLK  37               // blocks per batch -> 296 total = 2 per SM, single wave
#define NPART (BB * NBLK)      // 296 partial tiles
#define P     32               // pixels per stage (8 KB features)
#define NSTG  5                // ring depth -> ~80 KB/SM in flight
#define GROUPS_PER_B (HWPX / P)   // 8192 groups of 32 pixels
// 8192 = 37*221 + 15  -> first 15 blocks take 222 groups, rest 221
#define G_BASE 221
#define G_REM  15

// SMEM layout (bytes, all 16B-aligned)
#define OFF_ACC   0
#define OFF_CNT   (SS * CC * 4)              // 65536
#define OFF_MBAR  (OFF_CNT + SS * 4)         // 66560 : full[s]@+16s, empty[s]@+16s+8
#define OFF_LAB   (OFF_MBAR + NSTG * 16)     // 66640
#define OFF_FEAT  (OFF_LAB + NSTG * P * 4)   // 67280
#define SMEM_TOTAL (OFF_FEAT + NSTG * P * CC * 4)   // 67280 + 40960 = 108240
#define STAGE_TX  (P * CC * 4 + P * 4)       // 8320 bytes per stage

// Global scratch: per-block partials (no atomics, fully overwritten each call)
__device__ float g_part[(size_t)NPART * SS * CC];   // ~19.4 MB
__device__ float g_cnt[NPART * SS];

// ---------- minimal PTX helpers ----------
__device__ __forceinline__ uint32_t smem_u32(const void* p) {
    uint32_t a;
    asm("{ .reg .u64 t; cvta.to.shared.u64 t, %1; cvt.u32.u64 %0, t; }" : "=r"(a) : "l"(p));
    return a;
}
__device__ __forceinline__ void mbar_init(uint32_t a, uint32_t cnt) {
    asm volatile("mbarrier.init.shared.b64 [%0], %1;" :: "r"(a), "r"(cnt) : "memory");
}
__device__ __forceinline__ void mbar_expect_tx(uint32_t a, uint32_t bytes) {
    asm volatile("mbarrier.arrive.expect_tx.shared.b64 _, [%0], %1;" :: "r"(a), "r"(bytes) : "memory");
}
__device__ __forceinline__ void mbar_arrive(uint32_t a) {
    asm volatile("mbarrier.arrive.shared.b64 _, [%0];" :: "r"(a) : "memory");
}
__device__ __forceinline__ void mbar_wait_acq(uint32_t a, int ph) {
    asm volatile(
        "{\n\t.reg .pred p;\n\t"
        "WLA_%=:\n\t"
        "mbarrier.try_wait.parity.acquire.cta.shared::cta.b64 p, [%0], %1, 0x989680;\n\t"
        "@!p bra WLA_%=;\n\t}"
        :: "r"(a), "r"(ph) : "memory");
}
__device__ __forceinline__ void mbar_wait_rlx(uint32_t a, int ph) {
    asm volatile(
        "{\n\t.reg .pred p;\n\t"
        "WLR_%=:\n\t"
        "mbarrier.try_wait.parity.relaxed.cta.shared::cta.b64 p, [%0], %1, 0x989680;\n\t"
        "@!p bra WLR_%=;\n\t}"
        :: "r"(a), "r"(ph) : "memory");
}
__device__ __forceinline__ void bulk_g2s(uint32_t dst, const void* src, uint32_t bytes, uint32_t mbar) {
    asm volatile(
        "cp.async.bulk.shared::cluster.global.mbarrier::complete_tx::bytes [%0], [%1], %2, [%3];"
        :: "r"(dst), "l"(src), "r"(bytes), "r"(mbar) : "memory");
}
// -----------------------------------------

__global__ void __launch_bounds__(128, 2)
pool_kernel(const float* __restrict__ feat, const int* __restrict__ lab) {
    extern __shared__ char smem[];
    float* acc  = (float*)(smem + OFF_ACC);
    int*   scnt = (int*)(smem + OFF_CNT);
    const uint32_t sb = smem_u32(smem);

    const int tid = threadIdx.x;
    const int wid = tid >> 5;
    const int lane = tid & 31;

    // Zero per-block accumulators
    #pragma unroll 4
    for (int i = tid; i < SS * CC; i += 128) acc[i] = 0.0f;
    for (int i = tid; i < SS; i += 128) scnt[i] = 0;
    if (tid == 0) {
        #pragma unroll
        for (int s = 0; s < NSTG; s++) {
            mbar_init(sb + OFF_MBAR + s * 16,     1);   // full: producer arrive + tx
            mbar_init(sb + OFF_MBAR + s * 16 + 8, 96);  // empty: warps 0..2 arrive
        }
    }
    __syncthreads();

    const int bidx = blockIdx.x;        // 0..NPART-1
    const int b = bidx / NBLK;
    const int j = bidx % NBLK;
    const int ng     = G_BASE + (j < G_REM ? 1 : 0);
    const int base_g = j * G_BASE + (j < G_REM ? j : G_REM);

    const float* f = feat + (size_t)b * HWPX * CC;
    const int*   l = lab  + (size_t)b * HWPX;

    if (tid == 96) {
        // ---- producer: one bulk copy pair per 32-pixel tile ----
        int ph = 1, s = 0;
        for (int g = 0; g < ng; g++) {
            mbar_wait_rlx(sb + OFF_MBAR + s * 16 + 8, ph);
            const uint32_t ful = sb + OFF_MBAR + s * 16;
            mbar_expect_tx(ful, STAGE_TX);
            const size_t pix0 = (size_t)(base_g + g) * P;
            bulk_g2s(sb + OFF_FEAT + s * (P * CC * 4), f + pix0 * CC, P * CC * 4, ful);
            bulk_g2s(sb + OFF_LAB  + s * (P * 4),      l + pix0,      P * 4,      ful);
            if (++s == NSTG) { s = 0; ph ^= 1; }
        }
    } else if (wid < 2) {
        // ---- consumers: warp0 ch 0-31, warp1 ch 32-63; race-free RMW ----
        const int c = tid;              // channel
        int ph = 0, s = 0;
        for (int g = 0; g < ng; g++) {
            mbar_wait_acq(sb + OFF_MBAR + s * 16, ph);
            const int*   slab = (const int*)(smem + OFF_LAB + s * (P * 4));
            const float* sf   = (const float*)(smem + OFF_FEAT + s * (P * CC * 4));
            #pragma unroll 8
            for (int i = 0; i < P; i++) {
                const int lb = slab[i];                 // broadcast LDS
                acc[lb * CC + c] += sf[i * CC + c];     // conflict-free banks
            }
            mbar_arrive(sb + OFF_MBAR + s * 16 + 8);
            if (++s == NSTG) { s = 0; ph ^= 1; }
        }
    } else if (wid == 2) {
        // ---- counts warp: one smem atomic per pixel, spread addresses ----
        int ph = 0, s = 0;
        for (int g = 0; g < ng; g++) {
            mbar_wait_acq(sb + OFF_MBAR + s * 16, ph);
            const int* slab = (const int*)(smem + OFF_LAB + s * (P * 4));
            atomicAdd(&scnt[slab[lane]], 1);
            mbar_arrive(sb + OFF_MBAR + s * 16 + 8);
            if (++s == NSTG) { s = 0; ph ^= 1; }
        }
    }
    // warp3 lanes 97..127 fall through

    __syncthreads();

    // Flush partial tile (non-atomic, coalesced)
    float* gp = g_part + (size_t)bidx * SS * CC;
    #pragma unroll 4
    for (int i = tid; i < SS * CC; i += 128) gp[i] = acc[i];
    float* gc = g_cnt + bidx * SS;
    for (int i = tid; i < SS; i += 128) gc[i] = (float)scnt[i];
}

__global__ void mean_kernel(float* __restrict__ out) {
    const int i = blockIdx.x * blockDim.x + threadIdx.x;
    if (i >= BB * SS * CC) return;
    const int b  = i / (SS * CC);
    const int sc = i - b * (SS * CC);
    const int s  = sc >> 6;
    float sum = 0.0f, cnt = 0.0f;
    const int pb = b * NBLK;
    #pragma unroll 4
    for (int j = 0; j < NBLK; j++) {
        sum += g_part[(size_t)(pb + j) * (SS * CC) + sc];
        cnt += g_cnt[(pb + j) * SS + s];
    }
    out[i] = sum / fmaxf(cnt, 1.0f);
}

extern "C" void kernel_launch(void* const* d_in, const int* in_sizes, int n_in,
                              void* d_out, int out_size) {
    const float* feat = (const float*)d_in[0];
    const int*   lab  = (const int*)d_in[1];
    float*       out  = (float*)d_out;

    cudaFuncSetAttribute(pool_kernel,
                         cudaFuncAttributeMaxDynamicSharedMemorySize,
                         (int)SMEM_TOTAL);

    pool_kernel<<<NPART, 128, SMEM_TOTAL>>>(feat, lab);

    const int n = BB * SS * CC;
    mean_kernel<<<(n + 255) / 256, 256>>>(out);
}

// round 4
// speedup vs baseline: 4.4855x; 2.5663x over previous
#include <cuda_runtime.h>
#include <cstdint>

// Fixed problem shape
#define BB    8
#define HWPX  (512 * 512)
#define CC    64
#define SS    256

// Decomposition
#define NBLK  37                    // blocks per batch -> 296 = 2/SM, single wave
#define NPART (BB * NBLK)
#define P     32                    // pixels per stage (8 KB features)
#define NSTG  5
#define G_BASE 221                  // 8192 = 37*221 + 15
#define G_REM  15

#define NCW   16                    // consumer warps (label ranges of 16)
#define NWARPS (NCW + 2)            // + partition warp + producer warp
#define NTHR  (NWARPS * 32)         // 576

// SMEM layout (bytes)
#define OFF_ACC   0                                 // 65536  float2[256][32]
#define OFF_FEAT  (SS * CC * 4)                     // 65536, 5*8192 = 40960
#define OFF_LAB   (OFF_FEAT + NSTG * P * CC * 4)    // 106496, 640
#define OFF_LIST  (OFF_LAB + NSTG * P * 4)          // 107136, 5*16*32*2 = 5120
#define OFF_LCNT  (OFF_LIST + NSTG * NCW * 32 * 2)  // 112256, 320
#define OFF_SCNT  (OFF_LCNT + NSTG * NCW * 4)       // 112576, 1024
#define OFF_MBAR  (OFF_SCNT + SS * 4)               // 113600, 5*24 = 120
#define SMEM_TOTAL (OFF_MBAR + NSTG * 24)           // 113720 -> 2 CTAs/SM
#define STAGE_TX  (P * CC * 4 + P * 4)              // 8320

__device__ float g_part[(size_t)NPART * SS * CC];
__device__ float g_cnt[NPART * SS];

// ---------- PTX helpers ----------
__device__ __forceinline__ uint32_t smem_u32(const void* p) {
    uint32_t a;
    asm("{ .reg .u64 t; cvta.to.shared.u64 t, %1; cvt.u32.u64 %0, t; }" : "=r"(a) : "l"(p));
    return a;
}
__device__ __forceinline__ void mbar_init(uint32_t a, uint32_t cnt) {
    asm volatile("mbarrier.init.shared.b64 [%0], %1;" :: "r"(a), "r"(cnt) : "memory");
}
__device__ __forceinline__ void mbar_expect_tx(uint32_t a, uint32_t bytes) {
    asm volatile("mbarrier.arrive.expect_tx.shared.b64 _, [%0], %1;" :: "r"(a), "r"(bytes) : "memory");
}
__device__ __forceinline__ void mbar_arrive(uint32_t a) {
    asm volatile("mbarrier.arrive.shared.b64 _, [%0];" :: "r"(a) : "memory");
}
__device__ __forceinline__ void mbar_wait_acq(uint32_t a, int ph) {
    asm volatile(
        "{\n\t.reg .pred p;\n\t"
        "WLA_%=:\n\t"
        "mbarrier.try_wait.parity.acquire.cta.shared::cta.b64 p, [%0], %1, 0x989680;\n\t"
        "@!p bra WLA_%=;\n\t}"
        :: "r"(a), "r"(ph) : "memory");
}
__device__ __forceinline__ void mbar_wait_rlx(uint32_t a, int ph) {
    asm volatile(
        "{\n\t.reg .pred p;\n\t"
        "WLR_%=:\n\t"
        "mbarrier.try_wait.parity.relaxed.cta.shared::cta.b64 p, [%0], %1, 0x989680;\n\t"
        "@!p bra WLR_%=;\n\t}"
        :: "r"(a), "r"(ph) : "memory");
}
__device__ __forceinline__ void bulk_g2s(uint32_t dst, const void* src, uint32_t bytes, uint32_t mbar) {
    asm volatile(
        "cp.async.bulk.shared::cluster.global.mbarrier::complete_tx::bytes [%0], [%1], %2, [%3];"
        :: "r"(dst), "l"(src), "r"(bytes), "r"(mbar) : "memory");
}
// ----------------------------------

__global__ void __launch_bounds__(NTHR, 2)
pool_kernel(const float* __restrict__ feat, const int* __restrict__ lab) {
    extern __shared__ char smem[];
    float2*   acc2   = (float2*)(smem + OFF_ACC);          // [256][32] ch pairs
    float2*   sfeat2 = (float2*)(smem + OFF_FEAT);         // [NSTG*P][32]
    int*      slab   = (int*)(smem + OFF_LAB);             // [NSTG*P]
    uint16_t* slist  = (uint16_t*)(smem + OFF_LIST);       // [NSTG*NCW][32]
    int*      slcnt  = (int*)(smem + OFF_LCNT);            // [NSTG*NCW]
    int*      scnt   = (int*)(smem + OFF_SCNT);            // [SS]
    const uint32_t sb = smem_u32(smem);

    const int tid  = threadIdx.x;
    const int wid  = tid >> 5;
    const int lane = tid & 31;

    // Zero accumulators
    float* accf = (float*)acc2;
    #pragma unroll 4
    for (int i = tid; i < SS * CC; i += NTHR) accf[i] = 0.0f;
    for (int i = tid; i < SS; i += NTHR) scnt[i] = 0;
    if (tid == 0) {
        #pragma unroll
        for (int s = 0; s < NSTG; s++) {
            mbar_init(sb + OFF_MBAR + s * 24,      1);        // full (tx-based)
            mbar_init(sb + OFF_MBAR + s * 24 + 8,  1);        // ready (partition lane0)
            mbar_init(sb + OFF_MBAR + s * 24 + 16, NCW + 1);  // empty (consumers + partition)
        }
    }
    __syncthreads();

    const int bidx = blockIdx.x;
    const int b = bidx / NBLK;
    const int j = bidx % NBLK;
    const int ng     = G_BASE + (j < G_REM ? 1 : 0);
    const int base_g = j * G_BASE + (j < G_REM ? j : G_REM);

    const float* f = feat + (size_t)b * HWPX * CC;
    const int*   l = lab  + (size_t)b * HWPX;

    if (wid < NCW) {
        // ---- consumers: warp w owns labels [w*16, w*16+16), float2 per lane ----
        int ph = 0, s = 0;
        for (int g = 0; g < ng; g++) {
            mbar_wait_acq(sb + OFF_MBAR + s * 24 + 8, ph);       // ready
            const int n = slcnt[s * NCW + wid];                  // broadcast
            const uint16_t* lst = slist + (s * NCW + wid) * 32;
            const float2*   sf  = sfeat2 + (size_t)s * P * 32;
            for (int k = 0; k < n; k++) {
                const uint32_t e  = lst[k];                      // broadcast LDS.16
                const int lb = e & 255;
                const int i  = e >> 8;
                const float2 v = sf[i * 32 + lane];
                float2* a = &acc2[lb * 32 + lane];
                float2 av = *a;
                av.x += v.x; av.y += v.y;
                *a = av;
            }
            if (lane == 0) mbar_arrive(sb + OFF_MBAR + s * 24 + 16);
            if (++s == NSTG) { s = 0; ph ^= 1; }
        }
    } else if (wid == NCW) {
        // ---- partition warp: bucket the 32 pixels of each stage by label>>4 ----
        int ph = 0, s = 0;
        for (int g = 0; g < ng; g++) {
            mbar_wait_acq(sb + OFF_MBAR + s * 24, ph);           // full
            const int lb = slab[s * P + lane];
            const int bucket = lb >> 4;
            const unsigned same = __match_any_sync(0xffffffffu, bucket);
            const int pos = __popc(same & ((1u << lane) - 1u));
            const int cnt = __popc(same);
            if (lane < NCW) slcnt[s * NCW + lane] = 0;
            __syncwarp();
            slist[(s * NCW + bucket) * 32 + pos] = (uint16_t)(lb | (lane << 8));
            if (pos == 0) slcnt[s * NCW + bucket] = cnt;
            atomicAdd(&scnt[lb], 1);
            __syncwarp();
            if (lane == 0) {
                mbar_arrive(sb + OFF_MBAR + s * 24 + 8);         // ready
                mbar_arrive(sb + OFF_MBAR + s * 24 + 16);        // empty (labels done)
            }
            if (++s == NSTG) { s = 0; ph ^= 1; }
        }
    } else if (tid == NCW * 32 + 32) {
        // ---- producer thread ----
        int ph = 1, s = 0;
        for (int g = 0; g < ng; g++) {
            mbar_wait_rlx(sb + OFF_MBAR + s * 24 + 16, ph);      // empty
            const uint32_t ful = sb + OFF_MBAR + s * 24;
            mbar_expect_tx(ful, STAGE_TX);
            const size_t pix0 = (size_t)(base_g + g) * P;
            bulk_g2s(sb + OFF_FEAT + s * (P * CC * 4), f + pix0 * CC, P * CC * 4, ful);
            bulk_g2s(sb + OFF_LAB  + s * (P * 4),      l + pix0,      P * 4,      ful);
            if (++s == NSTG) { s = 0; ph ^= 1; }
        }
    }

    __syncthreads();

    // Flush partial tile (non-atomic, coalesced)
    float* gp = g_part + (size_t)bidx * SS * CC;
    #pragma unroll 4
    for (int i = tid; i < SS * CC; i += NTHR) gp[i] = accf[i];
    float* gc = g_cnt + bidx * SS;
    for (int i = tid; i < SS; i += NTHR) gc[i] = (float)scnt[i];
}

__global__ void mean_kernel(float* __restrict__ out) {
    const int i = blockIdx.x * blockDim.x + threadIdx.x;
    if (i >= BB * SS * CC) return;
    const int b  = i / (SS * CC);
    const int sc = i - b * (SS * CC);
    const int s  = sc >> 6;
    float sum = 0.0f, cnt = 0.0f;
    const int pb = b * NBLK;
    #pragma unroll 4
    for (int jj = 0; jj < NBLK; jj++) {
        sum += g_part[(size_t)(pb + jj) * (SS * CC) + sc];
        cnt += g_cnt[(pb + jj) * SS + s];
    }
    out[i] = sum / fmaxf(cnt, 1.0f);
}

extern "C" void kernel_launch(void* const* d_in, const int* in_sizes, int n_in,
                              void* d_out, int out_size) {
    const float* feat = (const float*)d_in[0];
    const int*   lab  = (const int*)d_in[1];
    float*       out  = (float*)d_out;

    cudaFuncSetAttribute(pool_kernel,
                         cudaFuncAttributeMaxDynamicSharedMemorySize,
                         (int)SMEM_TOTAL);

    pool_kernel<<<NPART, NTHR, SMEM_TOTAL>>>(feat, lab);

    const int n = BB * SS * CC;
    mean_kernel<<<(n + 255) / 256, 256>>>(out);
}

// round 5
// speedup vs baseline: 4.4983x; 1.0028x over previous
#include <cuda_runtime.h>
#include <cstdint>

// Fixed problem shape
#define BB    8
#define HWPX  (512 * 512)
#define CC    64
#define SS    256

// Decomposition
#define NBLK  37                    // blocks per batch -> 296 = 2/SM, single wave
#define NPART (BB * NBLK)
#define P     32                    // pixels per stage (8 KB features)
#define NSTG  5
#define G_BASE 221                  // 8192 = 37*221 + 15
#define G_REM  15

#define NCW   16                    // consumer warps (label ranges of 16)
#define NWARPS (NCW + 2)            // + partition warp + producer warp
#define NTHR  (NWARPS * 32)         // 576

// SMEM layout (bytes)
#define OFF_ACC   0                                 // 65536  float2[256][32]
#define OFF_FEAT  (SS * CC * 4)                     // 65536, 5*8192 = 40960
#define OFF_LAB   (OFF_FEAT + NSTG * P * CC * 4)    // 106496, 640
#define OFF_LIST  (OFF_LAB + NSTG * P * 4)          // 107136, 5*16*32*2 = 5120
#define OFF_LCNT  (OFF_LIST + NSTG * NCW * 32 * 2)  // 112256, 320
#define OFF_SCNT  (OFF_LCNT + NSTG * NCW * 4)       // 112576, 1024
#define OFF_MBAR  (OFF_SCNT + SS * 4)               // 113600, 5*24 = 120
#define SMEM_TOTAL (OFF_MBAR + NSTG * 24)           // 113720 -> 2 CTAs/SM
#define STAGE_TX  (P * CC * 4 + P * 4)              // 8320

// Global scratch as float4 so LDG.128/STG.128 alignment is guaranteed
__device__ float4 g_part4[(size_t)NPART * SS * CC / 4];   // ~19.4 MB
__device__ float  g_cnt[NPART * SS];

// ---------- PTX helpers ----------
__device__ __forceinline__ uint32_t smem_u32(const void* p) {
    uint32_t a;
    asm("{ .reg .u64 t; cvta.to.shared.u64 t, %1; cvt.u32.u64 %0, t; }" : "=r"(a) : "l"(p));
    return a;
}
__device__ __forceinline__ void mbar_init(uint32_t a, uint32_t cnt) {
    asm volatile("mbarrier.init.shared.b64 [%0], %1;" :: "r"(a), "r"(cnt) : "memory");
}
__device__ __forceinline__ void mbar_expect_tx(uint32_t a, uint32_t bytes) {
    asm volatile("mbarrier.arrive.expect_tx.shared.b64 _, [%0], %1;" :: "r"(a), "r"(bytes) : "memory");
}
__device__ __forceinline__ void mbar_arrive(uint32_t a) {
    asm volatile("mbarrier.arrive.shared.b64 _, [%0];" :: "r"(a) : "memory");
}
__device__ __forceinline__ void mbar_wait_acq(uint32_t a, int ph) {
    asm volatile(
        "{\n\t.reg .pred p;\n\t"
        "WLA_%=:\n\t"
        "mbarrier.try_wait.parity.acquire.cta.shared::cta.b64 p, [%0], %1, 0x989680;\n\t"
        "@!p bra WLA_%=;\n\t}"
        :: "r"(a), "r"(ph) : "memory");
}
__device__ __forceinline__ void mbar_wait_rlx(uint32_t a, int ph) {
    asm volatile(
        "{\n\t.reg .pred p;\n\t"
        "WLR_%=:\n\t"
        "mbarrier.try_wait.parity.relaxed.cta.shared::cta.b64 p, [%0], %1, 0x989680;\n\t"
        "@!p bra WLR_%=;\n\t}"
        :: "r"(a), "r"(ph) : "memory");
}
__device__ __forceinline__ void bulk_g2s(uint32_t dst, const void* src, uint32_t bytes, uint32_t mbar) {
    asm volatile(
        "cp.async.bulk.shared::cluster.global.mbarrier::complete_tx::bytes [%0], [%1], %2, [%3];"
        :: "r"(dst), "l"(src), "r"(bytes), "r"(mbar) : "memory");
}
// ----------------------------------

__global__ void __launch_bounds__(NTHR, 2)
pool_kernel(const float* __restrict__ feat, const int* __restrict__ lab) {
    extern __shared__ char smem[];
    float2*   acc2   = (float2*)(smem + OFF_ACC);          // [256][32] ch pairs
    float2*   sfeat2 = (float2*)(smem + OFF_FEAT);         // [NSTG*P][32]
    int*      slab   = (int*)(smem + OFF_LAB);             // [NSTG*P]
    uint16_t* slist  = (uint16_t*)(smem + OFF_LIST);       // [NSTG*NCW][32]
    int*      slcnt  = (int*)(smem + OFF_LCNT);            // [NSTG*NCW]
    int*      scnt   = (int*)(smem + OFF_SCNT);            // [SS]
    const uint32_t sb = smem_u32(smem);

    const int tid  = threadIdx.x;
    const int wid  = tid >> 5;
    const int lane = tid & 31;

    // Zero accumulators (vectorized STS.128)
    float4* acc4 = (float4*)acc2;
    #pragma unroll
    for (int i = tid; i < SS * CC / 4; i += NTHR) acc4[i] = make_float4(0.f, 0.f, 0.f, 0.f);
    for (int i = tid; i < SS; i += NTHR) scnt[i] = 0;
    if (tid == 0) {
        #pragma unroll
        for (int s = 0; s < NSTG; s++) {
            mbar_init(sb + OFF_MBAR + s * 24,      1);        // full (tx-based)
            mbar_init(sb + OFF_MBAR + s * 24 + 8,  1);        // ready (partition lane0)
            mbar_init(sb + OFF_MBAR + s * 24 + 16, NCW + 1);  // empty (consumers + partition)
        }
    }
    __syncthreads();

    const int bidx = blockIdx.x;
    const int b = bidx / NBLK;
    const int j = bidx % NBLK;
    const int ng     = G_BASE + (j < G_REM ? 1 : 0);
    const int base_g = j * G_BASE + (j < G_REM ? j : G_REM);

    const float* f = feat + (size_t)b * HWPX * CC;
    const int*   l = lab  + (size_t)b * HWPX;

    if (wid < NCW) {
        // ---- consumers: warp w owns labels [w*16, w*16+16), float2 per lane ----
        int ph = 0, s = 0;
        for (int g = 0; g < ng; g++) {
            mbar_wait_acq(sb + OFF_MBAR + s * 24 + 8, ph);       // ready
            const int n = slcnt[s * NCW + wid];                  // broadcast
            const uint16_t* lst = slist + (s * NCW + wid) * 32;
            const float2*   sf  = sfeat2 + (size_t)s * P * 32;
            for (int k = 0; k < n; k++) {
                const uint32_t e  = lst[k];                      // broadcast LDS.16
                const int lb = e & 255;
                const int i  = e >> 8;
                const float2 v = sf[i * 32 + lane];
                float2* a = &acc2[lb * 32 + lane];
                float2 av = *a;
                av.x += v.x; av.y += v.y;
                *a = av;
            }
            if (lane == 0) mbar_arrive(sb + OFF_MBAR + s * 24 + 16);
            if (++s == NSTG) { s = 0; ph ^= 1; }
        }
    } else if (wid == NCW) {
        // ---- partition warp: bucket the 32 pixels of each stage by label>>4 ----
        int ph = 0, s = 0;
        for (int g = 0; g < ng; g++) {
            mbar_wait_acq(sb + OFF_MBAR + s * 24, ph);           // full
            const int lb = slab[s * P + lane];
            const int bucket = lb >> 4;
            const unsigned same = __match_any_sync(0xffffffffu, bucket);
            const int pos = __popc(same & ((1u << lane) - 1u));
            const int cnt = __popc(same);
            if (lane < NCW) slcnt[s * NCW + lane] = 0;
            __syncwarp();
            slist[(s * NCW + bucket) * 32 + pos] = (uint16_t)(lb | (lane << 8));
            if (pos == 0) slcnt[s * NCW + bucket] = cnt;
            atomicAdd(&scnt[lb], 1);
            __syncwarp();
            if (lane == 0) {
                mbar_arrive(sb + OFF_MBAR + s * 24 + 8);         // ready
                mbar_arrive(sb + OFF_MBAR + s * 24 + 16);        // empty (labels done)
            }
            if (++s == NSTG) { s = 0; ph ^= 1; }
        }
    } else if (tid == NCW * 32 + 32) {
        // ---- producer thread ----
        int ph = 1, s = 0;
        for (int g = 0; g < ng; g++) {
            mbar_wait_rlx(sb + OFF_MBAR + s * 24 + 16, ph);      // empty
            const uint32_t ful = sb + OFF_MBAR + s * 24;
            mbar_expect_tx(ful, STAGE_TX);
            const size_t pix0 = (size_t)(base_g + g) * P;
            bulk_g2s(sb + OFF_FEAT + s * (P * CC * 4), f + pix0 * CC, P * CC * 4, ful);
            bulk_g2s(sb + OFF_LAB  + s * (P * 4),      l + pix0,      P * 4,      ful);
            if (++s == NSTG) { s = 0; ph ^= 1; }
        }
    }

    __syncthreads();

    // Flush partial tile (non-atomic, coalesced, STG.128)
    float4* gp = g_part4 + (size_t)bidx * (SS * CC / 4);
    #pragma unroll
    for (int i = tid; i < SS * CC / 4; i += NTHR) gp[i] = acc4[i];
    float* gc = g_cnt + bidx * SS;
    for (int i = tid; i < SS; i += NTHR) gc[i] = (float)scnt[i];
}

// float4-vectorized reduction over the 37 partials per batch
__global__ void mean_kernel(float4* __restrict__ out4) {
    const int i4 = blockIdx.x * blockDim.x + threadIdx.x;     // 0 .. BB*SS*CC/4-1
    if (i4 >= BB * SS * CC / 4) return;
    const int PER_B4 = SS * CC / 4;                           // 4096
    const int b   = i4 / PER_B4;
    const int sc4 = i4 - b * PER_B4;
    const int s   = sc4 >> 4;                                 // / (CC/4)
    const int pb  = b * NBLK;

    float4 sum = make_float4(0.f, 0.f, 0.f, 0.f);
    float  cnt = 0.0f;
    #pragma unroll
    for (int jj = 0; jj < NBLK; jj++) {
        const float4 v = g_part4[(size_t)(pb + jj) * PER_B4 + sc4];
        sum.x += v.x; sum.y += v.y; sum.z += v.z; sum.w += v.w;
        cnt += g_cnt[(pb + jj) * SS + s];
    }
    const float inv = 1.0f / fmaxf(cnt, 1.0f);
    sum.x *= inv; sum.y *= inv; sum.z *= inv; sum.w *= inv;
    out4[i4] = sum;
}

extern "C" void kernel_launch(void* const* d_in, const int* in_sizes, int n_in,
                              void* d_out, int out_size) {
    const float* feat = (const float*)d_in[0];
    const int*   lab  = (const int*)d_in[1];
    float4*      out4 = (float4*)d_out;

    cudaFuncSetAttribute(pool_kernel,
                         cudaFuncAttributeMaxDynamicSharedMemorySize,
                         (int)SMEM_TOTAL);

    pool_kernel<<<NPART, NTHR, SMEM_TOTAL>>>(feat, lab);

    const int n4 = BB * SS * CC / 4;                          // 32768
    mean_kernel<<<(n4 + 255) / 256, 256>>>(out4);
}

// round 6
// speedup vs baseline: 4.5898x; 1.0203x over previous
#include <cuda_runtime.h>
#include <cstdint>

// Fixed problem shape
#define BB    8
#define HWPX  (512 * 512)
#define CC    64
#define SS    256

// Decomposition
#define NBLK  37                    // blocks per batch -> 296 = 2/SM, single wave
#define NPART (BB * NBLK)
#define P     32                    // pixels per stage (8 KB features)
#define NSTG  5
#define G_BASE 221                  // 8192 = 37*221 + 15
#define G_REM  15

#define NCW   16                    // consumer warps (label ranges of 16)
#define NWARPS (NCW + 2)            // + partition warp + producer warp
#define NTHR  (NWARPS * 32)         // 576

// SMEM layout (bytes)
#define OFF_ACC   0                                 // 65536  float2[256][32]
#define OFF_FEAT  (SS * CC * 4)                     // 65536, 5*8192 = 40960
#define OFF_LAB   (OFF_FEAT + NSTG * P * CC * 4)    // 106496, 640
#define OFF_LIST  (OFF_LAB + NSTG * P * 4)          // 107136, 5*16*32*2 = 5120
#define OFF_LCNT  (OFF_LIST + NSTG * NCW * 32 * 2)  // 112256, 320
#define OFF_SCNT  (OFF_LCNT + NSTG * NCW * 4)       // 112576, 1024
#define OFF_MBAR  (OFF_SCNT + SS * 4)               // 113600, 5*24 = 120
#define SMEM_TOTAL (OFF_MBAR + NSTG * 24)           // 113720 -> 2 CTAs/SM
#define STAGE_TX  (P * CC * 4 + P * 4)              // 8320

// Global scratch as float4 so LDG.128/STG.128 alignment is guaranteed
__device__ float4 g_part4[(size_t)NPART * SS * CC / 4];   // ~19.4 MB
__device__ float  g_cnt[NPART * SS];

// ---------- PTX helpers ----------
__device__ __forceinline__ uint32_t smem_u32(const void* p) {
    uint32_t a;
    asm("{ .reg .u64 t; cvta.to.shared.u64 t, %1; cvt.u32.u64 %0, t; }" : "=r"(a) : "l"(p));
    return a;
}
__device__ __forceinline__ void mbar_init(uint32_t a, uint32_t cnt) {
    asm volatile("mbarrier.init.shared.b64 [%0], %1;" :: "r"(a), "r"(cnt) : "memory");
}
__device__ __forceinline__ void mbar_expect_tx(uint32_t a, uint32_t bytes) {
    asm volatile("mbarrier.arrive.expect_tx.shared.b64 _, [%0], %1;" :: "r"(a), "r"(bytes) : "memory");
}
__device__ __forceinline__ void mbar_arrive(uint32_t a) {
    asm volatile("mbarrier.arrive.shared.b64 _, [%0];" :: "r"(a) : "memory");
}
__device__ __forceinline__ void mbar_wait_acq(uint32_t a, int ph) {
    asm volatile(
        "{\n\t.reg .pred p;\n\t"
        "WLA_%=:\n\t"
        "mbarrier.try_wait.parity.acquire.cta.shared::cta.b64 p, [%0], %1, 0x989680;\n\t"
        "@!p bra WLA_%=;\n\t}"
        :: "r"(a), "r"(ph) : "memory");
}
__device__ __forceinline__ void mbar_wait_rlx(uint32_t a, int ph) {
    asm volatile(
        "{\n\t.reg .pred p;\n\t"
        "WLR_%=:\n\t"
        "mbarrier.try_wait.parity.relaxed.cta.shared::cta.b64 p, [%0], %1, 0x989680;\n\t"
        "@!p bra WLR_%=;\n\t}"
        :: "r"(a), "r"(ph) : "memory");
}
__device__ __forceinline__ void bulk_g2s(uint32_t dst, const void* src, uint32_t bytes, uint32_t mbar) {
    asm volatile(
        "cp.async.bulk.shared::cluster.global.mbarrier::complete_tx::bytes [%0], [%1], %2, [%3];"
        :: "r"(dst), "l"(src), "r"(bytes), "r"(mbar) : "memory");
}
// ----------------------------------

__global__ void __launch_bounds__(NTHR, 2)
pool_kernel(const float* __restrict__ feat, const int* __restrict__ lab) {
    extern __shared__ char smem[];
    float2*   acc2   = (float2*)(smem + OFF_ACC);          // [256][32] ch pairs
    float2*   sfeat2 = (float2*)(smem + OFF_FEAT);         // [NSTG*P][32]
    int*      slab   = (int*)(smem + OFF_LAB);             // [NSTG*P]
    uint16_t* slist  = (uint16_t*)(smem + OFF_LIST);       // [NSTG*NCW][32]
    int*      slcnt  = (int*)(smem + OFF_LCNT);            // [NSTG*NCW]
    int*      scnt   = (int*)(smem + OFF_SCNT);            // [SS]
    const uint32_t sb = smem_u32(smem);

    const int tid  = threadIdx.x;
    const int wid  = tid >> 5;
    const int lane = tid & 31;

    // Zero accumulators (vectorized STS.128)
    float4* acc4 = (float4*)acc2;
    #pragma unroll
    for (int i = tid; i < SS * CC / 4; i += NTHR) acc4[i] = make_float4(0.f, 0.f, 0.f, 0.f);
    for (int i = tid; i < SS; i += NTHR) scnt[i] = 0;
    if (tid == 0) {
        #pragma unroll
        for (int s = 0; s < NSTG; s++) {
            mbar_init(sb + OFF_MBAR + s * 24,      1);        // full (tx-based)
            mbar_init(sb + OFF_MBAR + s * 24 + 8,  1);        // ready (partition lane0)
            mbar_init(sb + OFF_MBAR + s * 24 + 16, NCW + 1);  // empty (consumers + partition)
        }
    }
    __syncthreads();

    const int bidx = blockIdx.x;
    const int b = bidx / NBLK;
    const int j = bidx % NBLK;
    const int ng     = G_BASE + (j < G_REM ? 1 : 0);
    const int base_g = j * G_BASE + (j < G_REM ? j : G_REM);

    const float* f = feat + (size_t)b * HWPX * CC;
    const int*   l = lab  + (size_t)b * HWPX;

    if (wid < NCW) {
        // ---- consumers: warp w owns labels [w*16, w*16+16), float2 per lane ----
        int ph = 0, s = 0;
        for (int g = 0; g < ng; g++) {
            mbar_wait_acq(sb + OFF_MBAR + s * 24 + 8, ph);       // ready
            const int n = slcnt[s * NCW + wid];                  // broadcast
            const uint16_t* lst = slist + (s * NCW + wid) * 32;
            const float2*   sf  = sfeat2 + (size_t)s * P * 32;
            for (int k = 0; k < n; k++) {
                const uint32_t e  = lst[k];                      // broadcast LDS.16
                const int lb = e & 255;
                const int i  = e >> 8;
                const float2 v = sf[i * 32 + lane];
                float2* a = &acc2[lb * 32 + lane];
                float2 av = *a;
                av.x += v.x; av.y += v.y;
                *a = av;
            }
            if (lane == 0) mbar_arrive(sb + OFF_MBAR + s * 24 + 16);
            if (++s == NSTG) { s = 0; ph ^= 1; }
        }
    } else if (wid == NCW) {
        // ---- partition warp: bucket the 32 pixels of each stage by label>>4 ----
        int ph = 0, s = 0;
        for (int g = 0; g < ng; g++) {
            mbar_wait_acq(sb + OFF_MBAR + s * 24, ph);           // full
            const int lb = slab[s * P + lane];
            const int bucket = lb >> 4;
            const unsigned same = __match_any_sync(0xffffffffu, bucket);
            const int pos = __popc(same & ((1u << lane) - 1u));
            const int cnt = __popc(same);
            if (lane < NCW) slcnt[s * NCW + lane] = 0;
            __syncwarp();
            slist[(s * NCW + bucket) * 32 + pos] = (uint16_t)(lb | (lane << 8));
            if (pos == 0) slcnt[s * NCW + bucket] = cnt;
            atomicAdd(&scnt[lb], 1);
            __syncwarp();
            if (lane == 0) {
                mbar_arrive(sb + OFF_MBAR + s * 24 + 8);         // ready
                mbar_arrive(sb + OFF_MBAR + s * 24 + 16);        // empty (labels done)
            }
            if (++s == NSTG) { s = 0; ph ^= 1; }
        }
    } else if (tid == NCW * 32 + 32) {
        // ---- producer thread ----
        int ph = 1, s = 0;
        for (int g = 0; g < ng; g++) {
            mbar_wait_rlx(sb + OFF_MBAR + s * 24 + 16, ph);      // empty
            const uint32_t ful = sb + OFF_MBAR + s * 24;
            mbar_expect_tx(ful, STAGE_TX);
            const size_t pix0 = (size_t)(base_g + g) * P;
            bulk_g2s(sb + OFF_FEAT + s * (P * CC * 4), f + pix0 * CC, P * CC * 4, ful);
            bulk_g2s(sb + OFF_LAB  + s * (P * 4),      l + pix0,      P * 4,      ful);
            if (++s == NSTG) { s = 0; ph ^= 1; }
        }
    }

    __syncthreads();

    // Flush partial tile (non-atomic, coalesced, STG.128)
    float4* gp = g_part4 + (size_t)bidx * (SS * CC / 4);
    #pragma unroll
    for (int i = tid; i < SS * CC / 4; i += NTHR) gp[i] = acc4[i];
    float* gc = g_cnt + bidx * SS;
    for (int i = tid; i < SS; i += NTHR) gc[i] = (float)scnt[i];
}

// Split reduction: 64 outputs/block, 4 reducer threads per output.
// tid = o + 64*r  (o = output slot, r = reducer). Lanes within a warp have
// consecutive o -> consecutive sc4 -> coalesced LDG.128.
#define MO 64                        // outputs per block
#define MR 4                         // reducers per output
__global__ void __launch_bounds__(MO * MR, 8)
mean_kernel(float4* __restrict__ out4) {
    __shared__ float4 psum[MO * MR];
    __shared__ float  pcnt[MO * MR];

    const int tid = threadIdx.x;
    const int o   = tid & (MO - 1);
    const int r   = tid >> 6;

    const int PER_B4 = SS * CC / 4;                     // 4096
    const int i4   = blockIdx.x * MO + o;               // global output idx
    const int b    = i4 / PER_B4;
    const int sc4  = i4 - b * PER_B4;
    const int s    = sc4 >> 4;                          // segment id within batch
    const int pb   = b * NBLK;

    float4 sum = make_float4(0.f, 0.f, 0.f, 0.f);
    float  cnt = 0.0f;
    #pragma unroll
    for (int jj = r; jj < NBLK; jj += MR) {             // 9-10 independent LDG.128
        const float4 v = g_part4[(size_t)(pb + jj) * PER_B4 + sc4];
        sum.x += v.x; sum.y += v.y; sum.z += v.z; sum.w += v.w;
        cnt += g_cnt[(pb + jj) * SS + s];
    }
    psum[tid] = sum;
    pcnt[tid] = cnt;
    __syncthreads();

    if (tid < MO) {
        float4 t = psum[tid];
        float  c = pcnt[tid];
        #pragma unroll
        for (int q = 1; q < MR; q++) {
            const float4 u = psum[tid + q * MO];
            t.x += u.x; t.y += u.y; t.z += u.z; t.w += u.w;
            c += pcnt[tid + q * MO];
        }
        const float inv = 1.0f / fmaxf(c, 1.0f);
        t.x *= inv; t.y *= inv; t.z *= inv; t.w *= inv;
        out4[blockIdx.x * MO + tid] = t;
    }
}

extern "C" void kernel_launch(void* const* d_in, const int* in_sizes, int n_in,
                              void* d_out, int out_size) {
    const float* feat = (const float*)d_in[0];
    const int*   lab  = (const int*)d_in[1];
    float4*      out4 = (float4*)d_out;

    cudaFuncSetAttribute(pool_kernel,
                         cudaFuncAttributeMaxDynamicSharedMemorySize,
                         (int)SMEM_TOTAL);

    pool_kernel<<<NPART, NTHR, SMEM_TOTAL>>>(feat, lab);

    const int n4 = BB * SS * CC / 4;                    // 32768
    mean_kernel<<<n4 / MO, MO * MR>>>(out4);            // 512 blocks x 256 thr
}

// round 7
// speedup vs baseline: 4.7637x; 1.0379x over previous
#include <cuda_runtime.h>
#include <cstdint>

// Fixed problem shape
#define BB    8
#define HWPX  (512 * 512)
#define CC    64
#define SS    256

// Decomposition
#define NBLK  37                    // blocks per batch -> 296 = 2/SM, single wave
#define NPART (BB * NBLK)
#define P     32                    // pixels per stage (8 KB features)
#define NSTG  5
#define G_BASE 221                  // 8192 = 37*221 + 15
#define G_REM  15

#define NCW   16                    // consumer warps (label ranges of 16)
#define NWARPS (NCW + 2)            // + partition warp + producer warp
#define NTHR  (NWARPS * 32)         // 576

// SMEM layout (bytes)
#define OFF_ACC   0                                 // 65536  float2[256][32]
#define OFF_FEAT  (SS * CC * 4)                     // 65536, 5*8192 = 40960
#define OFF_LAB   (OFF_FEAT + NSTG * P * CC * 4)    // 106496, 640
#define OFF_LIST  (OFF_LAB + NSTG * P * 4)          // 107136, 5*16*32*2 = 5120
#define OFF_LCNT  (OFF_LIST + NSTG * NCW * 32 * 2)  // 112256, 320
#define OFF_SCNT  (OFF_LCNT + NSTG * NCW * 4)       // 112576, 1024
#define OFF_MBAR  (OFF_SCNT + SS * 4)               // 113600, 5*24 = 120
#define SMEM_TOTAL (OFF_MBAR + NSTG * 24)           // 113720 -> 2 CTAs/SM
#define STAGE_TX  (P * CC * 4 + P * 4)              // 8320

// L2-resident atomic accumulation buffers (zero-initialized at module load;
// mean_kernel re-zeros them after every read, so the invariant holds for
// every subsequent kernel_launch call / graph replay).
__device__ float4 g_sums4[BB * SS * CC / 4];   // 2 MB
__device__ float  g_cntg[BB * SS];             // 8 KB

// ---------- PTX helpers ----------
__device__ __forceinline__ uint32_t smem_u32(const void* p) {
    uint32_t a;
    asm("{ .reg .u64 t; cvta.to.shared.u64 t, %1; cvt.u32.u64 %0, t; }" : "=r"(a) : "l"(p));
    return a;
}
__device__ __forceinline__ void mbar_init(uint32_t a, uint32_t cnt) {
    asm volatile("mbarrier.init.shared.b64 [%0], %1;" :: "r"(a), "r"(cnt) : "memory");
}
__device__ __forceinline__ void mbar_expect_tx(uint32_t a, uint32_t bytes) {
    asm volatile("mbarrier.arrive.expect_tx.shared.b64 _, [%0], %1;" :: "r"(a), "r"(bytes) : "memory");
}
__device__ __forceinline__ void mbar_arrive(uint32_t a) {
    asm volatile("mbarrier.arrive.shared.b64 _, [%0];" :: "r"(a) : "memory");
}
__device__ __forceinline__ void mbar_wait_acq(uint32_t a, int ph) {
    asm volatile(
        "{\n\t.reg .pred p;\n\t"
        "WLA_%=:\n\t"
        "mbarrier.try_wait.parity.acquire.cta.shared::cta.b64 p, [%0], %1, 0x989680;\n\t"
        "@!p bra WLA_%=;\n\t}"
        :: "r"(a), "r"(ph) : "memory");
}
__device__ __forceinline__ void mbar_wait_rlx(uint32_t a, int ph) {
    asm volatile(
        "{\n\t.reg .pred p;\n\t"
        "WLR_%=:\n\t"
        "mbarrier.try_wait.parity.relaxed.cta.shared::cta.b64 p, [%0], %1, 0x989680;\n\t"
        "@!p bra WLR_%=;\n\t}"
        :: "r"(a), "r"(ph) : "memory");
}
__device__ __forceinline__ void bulk_g2s(uint32_t dst, const void* src, uint32_t bytes, uint32_t mbar) {
    asm volatile(
        "cp.async.bulk.shared::cluster.global.mbarrier::complete_tx::bytes [%0], [%1], %2, [%3];"
        :: "r"(dst), "l"(src), "r"(bytes), "r"(mbar) : "memory");
}
// Vector reduction (no return) to global: sm_90+ red.global.add.v4.f32
__device__ __forceinline__ void redg_add_v4(float4* p, float4 v) {
    asm volatile("red.global.add.v4.f32 [%0], {%1, %2, %3, %4};"
                 :: "l"(p), "f"(v.x), "f"(v.y), "f"(v.z), "f"(v.w) : "memory");
}
__device__ __forceinline__ void redg_add_f32(float* p, float v) {
    asm volatile("red.global.add.f32 [%0], %1;" :: "l"(p), "f"(v) : "memory");
}
// ----------------------------------

__global__ void __launch_bounds__(NTHR, 2)
pool_kernel(const float* __restrict__ feat, const int* __restrict__ lab) {
    extern __shared__ char smem[];
    float2*   acc2   = (float2*)(smem + OFF_ACC);          // [256][32] ch pairs
    float2*   sfeat2 = (float2*)(smem + OFF_FEAT);         // [NSTG*P][32]
    int*      slab   = (int*)(smem + OFF_LAB);             // [NSTG*P]
    uint16_t* slist  = (uint16_t*)(smem + OFF_LIST);       // [NSTG*NCW][32]
    int*      slcnt  = (int*)(smem + OFF_LCNT);            // [NSTG*NCW]
    int*      scnt   = (int*)(smem + OFF_SCNT);            // [SS]
    const uint32_t sb = smem_u32(smem);

    const int tid  = threadIdx.x;
    const int wid  = tid >> 5;
    const int lane = tid & 31;

    // Zero accumulators (vectorized STS.128)
    float4* acc4 = (float4*)acc2;
    #pragma unroll
    for (int i = tid; i < SS * CC / 4; i += NTHR) acc4[i] = make_float4(0.f, 0.f, 0.f, 0.f);
    for (int i = tid; i < SS; i += NTHR) scnt[i] = 0;
    if (tid == 0) {
        #pragma unroll
        for (int s = 0; s < NSTG; s++) {
            mbar_init(sb + OFF_MBAR + s * 24,      1);        // full (tx-based)
            mbar_init(sb + OFF_MBAR + s * 24 + 8,  1);        // ready (partition lane0)
            mbar_init(sb + OFF_MBAR + s * 24 + 16, NCW + 1);  // empty (consumers + partition)
        }
    }
    __syncthreads();

    const int bidx = blockIdx.x;
    const int b = bidx / NBLK;
    const int j = bidx % NBLK;
    const int ng     = G_BASE + (j < G_REM ? 1 : 0);
    const int base_g = j * G_BASE + (j < G_REM ? j : G_REM);

    const float* f = feat + (size_t)b * HWPX * CC;
    const int*   l = lab  + (size_t)b * HWPX;

    if (wid < NCW) {
        // ---- consumers: warp w owns labels [w*16, w*16+16), float2 per lane ----
        int ph = 0, s = 0;
        for (int g = 0; g < ng; g++) {
            mbar_wait_acq(sb + OFF_MBAR + s * 24 + 8, ph);       // ready
            const int n = slcnt[s * NCW + wid];                  // broadcast
            const uint16_t* lst = slist + (s * NCW + wid) * 32;
            const float2*   sf  = sfeat2 + (size_t)s * P * 32;
            for (int k = 0; k < n; k++) {
                const uint32_t e  = lst[k];                      // broadcast LDS.16
                const int lb = e & 255;
                const int i  = e >> 8;
                const float2 v = sf[i * 32 + lane];
                float2* a = &acc2[lb * 32 + lane];
                float2 av = *a;
                av.x += v.x; av.y += v.y;
                *a = av;
            }
            if (lane == 0) mbar_arrive(sb + OFF_MBAR + s * 24 + 16);
            if (++s == NSTG) { s = 0; ph ^= 1; }
        }
    } else if (wid == NCW) {
        // ---- partition warp: bucket the 32 pixels of each stage by label>>4 ----
        int ph = 0, s = 0;
        for (int g = 0; g < ng; g++) {
            mbar_wait_acq(sb + OFF_MBAR + s * 24, ph);           // full
            const int lb = slab[s * P + lane];
            const int bucket = lb >> 4;
            const unsigned same = __match_any_sync(0xffffffffu, bucket);
            const int pos = __popc(same & ((1u << lane) - 1u));
            const int cnt = __popc(same);
            if (lane < NCW) slcnt[s * NCW + lane] = 0;
            __syncwarp();
            slist[(s * NCW + bucket) * 32 + pos] = (uint16_t)(lb | (lane << 8));
            if (pos == 0) slcnt[s * NCW + bucket] = cnt;
            atomicAdd(&scnt[lb], 1);
            __syncwarp();
            if (lane == 0) {
                mbar_arrive(sb + OFF_MBAR + s * 24 + 8);         // ready
                mbar_arrive(sb + OFF_MBAR + s * 24 + 16);        // empty (labels done)
            }
            if (++s == NSTG) { s = 0; ph ^= 1; }
        }
    } else if (tid == NCW * 32 + 32) {
        // ---- producer thread ----
        int ph = 1, s = 0;
        for (int g = 0; g < ng; g++) {
            mbar_wait_rlx(sb + OFF_MBAR + s * 24 + 16, ph);      // empty
            const uint32_t ful = sb + OFF_MBAR + s * 24;
            mbar_expect_tx(ful, STAGE_TX);
            const size_t pix0 = (size_t)(base_g + g) * P;
            bulk_g2s(sb + OFF_FEAT + s * (P * CC * 4), f + pix0 * CC, P * CC * 4, ful);
            bulk_g2s(sb + OFF_LAB  + s * (P * 4),      l + pix0,      P * 4,      ful);
            if (++s == NSTG) { s = 0; ph ^= 1; }
        }
    }

    __syncthreads();

    // Flush into L2-resident final buffer via vector REDG (no DRAM scratch).
    float4* gs = g_sums4 + (size_t)b * (SS * CC / 4);
    #pragma unroll
    for (int i = tid; i < SS * CC / 4; i += NTHR) redg_add_v4(&gs[i], acc4[i]);
    float* gc = g_cntg + b * SS;
    for (int i = tid; i < SS; i += NTHR) redg_add_f32(&gc[i], (float)scnt[i]);
}

// Finalize: pure L2 traffic. Reads sums+counts, writes means, then re-zeros
// the scratch so the next kernel_launch call starts clean.
__global__ void __launch_bounds__(256)
mean_kernel(float4* __restrict__ out4) {
    const int i4 = blockIdx.x * 256 + threadIdx.x;      // 0 .. 32767
    const int PER_B4 = SS * CC / 4;                     // 4096
    const int b   = i4 / PER_B4;
    const int sc4 = i4 - b * PER_B4;
    const int s   = sc4 >> 4;                           // 16 float4 per segment

    const float4 v = g_sums4[i4];
    const float  c = g_cntg[b * SS + s];
    const float inv = 1.0f / fmaxf(c, 1.0f);
    out4[i4] = make_float4(v.x * inv, v.y * inv, v.z * inv, v.w * inv);
    g_sums4[i4] = make_float4(0.f, 0.f, 0.f, 0.f);

    __syncthreads();   // all 16 readers of this segment's count are in this block
    if ((sc4 & 15) == 0) g_cntg[b * SS + s] = 0.0f;
}

extern "C" void kernel_launch(void* const* d_in, const int* in_sizes, int n_in,
                              void* d_out, int out_size) {
    const float* feat = (const float*)d_in[0];
    const int*   lab  = (const int*)d_in[1];
    float4*      out4 = (float4*)d_out;

    cudaFuncSetAttribute(pool_kernel,
                         cudaFuncAttributeMaxDynamicSharedMemorySize,
                         (int)SMEM_TOTAL);

    pool_kernel<<<NPART, NTHR, SMEM_TOTAL>>>(feat, lab);

    const int n4 = BB * SS * CC / 4;                    // 32768
    mean_kernel<<<n4 / 256, 256>>>(out4);
}

// round 8
// speedup vs baseline: 4.7877x; 1.0051x over previous
#include <cuda_runtime.h>
#include <cstdint>

// Fixed problem shape
#define BB    8
#define HWPX  (512 * 512)
#define CC    64
#define SS    256

// Decomposition
#define NBLK  37                    // blocks per batch -> 296 = 2/SM, single wave
#define NPART (BB * NBLK)
#define P     32                    // pixels per stage (8 KB features)
#define NSTG  5
#define G_BASE 221                  // 8192 = 37*221 + 15
#define G_REM  15

#define NCW   16                    // consumer warps (label ranges of 16)
#define NWARPS (NCW + 2)            // + partition warp + producer warp
#define NTHR  (NWARPS * 32)         // 576

// SMEM layout (bytes)
#define OFF_ACC   0                                 // 65536  float2[256][32]
#define OFF_FEAT  (SS * CC * 4)                     // 65536, 5*8192 = 40960
#define OFF_LAB   (OFF_FEAT + NSTG * P * CC * 4)    // 106496, 640
#define OFF_LIST  (OFF_LAB + NSTG * P * 4)          // 107136, 5*16*32*2 = 5120
#define OFF_LCNT  (OFF_LIST + NSTG * NCW * 32 * 2)  // 112256, 320
#define OFF_SCNT  (OFF_LCNT + NSTG * NCW * 4)       // 112576, 1024
#define OFF_MBAR  (OFF_SCNT + SS * 4)               // 113600, 5*24 = 120
#define SMEM_TOTAL (OFF_MBAR + NSTG * 24)           // 113720 -> 2 CTAs/SM
#define STAGE_TX  (P * CC * 4 + P * 4)              // 8320

// L2-resident atomic accumulation buffers (zero-initialized at module load;
// mean_kernel re-zeros them after every read, so the invariant holds for
// every subsequent kernel_launch call / graph replay).
__device__ float4 g_sums4[BB * SS * CC / 4];   // 2 MB
__device__ float  g_cntg[BB * SS];             // 8 KB

// ---------- PTX helpers ----------
__device__ __forceinline__ uint32_t smem_u32(const void* p) {
    uint32_t a;
    asm("{ .reg .u64 t; cvta.to.shared.u64 t, %1; cvt.u32.u64 %0, t; }" : "=r"(a) : "l"(p));
    return a;
}
__device__ __forceinline__ void mbar_init(uint32_t a, uint32_t cnt) {
    asm volatile("mbarrier.init.shared.b64 [%0], %1;" :: "r"(a), "r"(cnt) : "memory");
}
__device__ __forceinline__ void mbar_expect_tx(uint32_t a, uint32_t bytes) {
    asm volatile("mbarrier.arrive.expect_tx.shared.b64 _, [%0], %1;" :: "r"(a), "r"(bytes) : "memory");
}
__device__ __forceinline__ void mbar_arrive(uint32_t a) {
    asm volatile("mbarrier.arrive.shared.b64 _, [%0];" :: "r"(a) : "memory");
}
__device__ __forceinline__ void mbar_wait_acq(uint32_t a, int ph) {
    asm volatile(
        "{\n\t.reg .pred p;\n\t"
        "WLA_%=:\n\t"
        "mbarrier.try_wait.parity.acquire.cta.shared::cta.b64 p, [%0], %1, 0x989680;\n\t"
        "@!p bra WLA_%=;\n\t}"
        :: "r"(a), "r"(ph) : "memory");
}
__device__ __forceinline__ void mbar_wait_rlx(uint32_t a, int ph) {
    asm volatile(
        "{\n\t.reg .pred p;\n\t"
        "WLR_%=:\n\t"
        "mbarrier.try_wait.parity.relaxed.cta.shared::cta.b64 p, [%0], %1, 0x989680;\n\t"
        "@!p bra WLR_%=;\n\t}"
        :: "r"(a), "r"(ph) : "memory");
}
__device__ __forceinline__ void bulk_g2s(uint32_t dst, const void* src, uint32_t bytes, uint32_t mbar) {
    asm volatile(
        "cp.async.bulk.shared::cluster.global.mbarrier::complete_tx::bytes [%0], [%1], %2, [%3];"
        :: "r"(dst), "l"(src), "r"(bytes), "r"(mbar) : "memory");
}
// Vector reduction (no return) to global: sm_90+ red.global.add.v4.f32
__device__ __forceinline__ void redg_add_v4(float4* p, float4 v) {
    asm volatile("red.global.add.v4.f32 [%0], {%1, %2, %3, %4};"
                 :: "l"(p), "f"(v.x), "f"(v.y), "f"(v.z), "f"(v.w) : "memory");
}
__device__ __forceinline__ void redg_add_f32(float* p, float v) {
    asm volatile("red.global.add.f32 [%0], %1;" :: "l"(p), "f"(v) : "memory");
}
// ----------------------------------

__global__ void __launch_bounds__(NTHR, 2)
pool_kernel(const float* __restrict__ feat, const int* __restrict__ lab) {
    extern __shared__ char smem[];
    float2*   acc2   = (float2*)(smem + OFF_ACC);          // [256][32] ch pairs
    float2*   sfeat2 = (float2*)(smem + OFF_FEAT);         // [NSTG*P][32]
    int*      slab   = (int*)(smem + OFF_LAB);             // [NSTG*P]
    uint16_t* slist  = (uint16_t*)(smem + OFF_LIST);       // [NSTG*NCW][32]
    int*      slcnt  = (int*)(smem + OFF_LCNT);            // [NSTG*NCW]
    int*      scnt   = (int*)(smem + OFF_SCNT);            // [SS]
    const uint32_t sb = smem_u32(smem);

    const int tid  = threadIdx.x;
    const int wid  = tid >> 5;
    const int lane = tid & 31;

    if (tid == 0) {
        #pragma unroll
        for (int s = 0; s < NSTG; s++) {
            mbar_init(sb + OFF_MBAR + s * 24,      1);        // full (tx-based)
            mbar_init(sb + OFF_MBAR + s * 24 + 8,  1);        // ready (partition lane0)
            mbar_init(sb + OFF_MBAR + s * 24 + 16, NCW + 1);  // empty (consumers + partition)
        }
    }
    __syncthreads();   // mbars visible to producer before any TMA

    const int bidx = blockIdx.x;
    const int b = bidx / NBLK;
    const int j = bidx % NBLK;
    const int ng     = G_BASE + (j < G_REM ? 1 : 0);
    const int base_g = j * G_BASE + (j < G_REM ? j : G_REM);

    const float* f = feat + (size_t)b * HWPX * CC;
    const int*   l = lab  + (size_t)b * HWPX;

    if (wid < NCW) {
        // ---- consumers: warp w owns labels [w*16, w*16+16), float2 per lane ----
        // Zero OWN accumulator rows (race-free: only this warp touches them),
        // overlapped with the producer's first TMA in flight.
        {
            float2 z = make_float2(0.f, 0.f);
            float2* arow = &acc2[(wid * 16) * 32 + lane];
            #pragma unroll
            for (int r = 0; r < 16; r++) arow[r * 32] = z;
        }
        int ph = 0, s = 0;
        for (int g = 0; g < ng; g++) {
            mbar_wait_acq(sb + OFF_MBAR + s * 24 + 8, ph);       // ready
            const int n = slcnt[s * NCW + wid];                  // broadcast
            const uint16_t* lst = slist + (s * NCW + wid) * 32;
            const float2*   sf  = sfeat2 + (size_t)s * P * 32;
            for (int k = 0; k < n; k++) {
                const uint32_t e  = lst[k];                      // broadcast LDS.16
                const int lb = e & 255;
                const int i  = e >> 8;
                const float2 v = sf[i * 32 + lane];
                float2* a = &acc2[lb * 32 + lane];
                float2 av = *a;
                av.x += v.x; av.y += v.y;
                *a = av;
            }
            if (lane == 0) mbar_arrive(sb + OFF_MBAR + s * 24 + 16);
            if (++s == NSTG) { s = 0; ph ^= 1; }
        }
    } else if (wid == NCW) {
        // ---- partition warp: bucket the 32 pixels of each stage by label>>4 ----
        #pragma unroll
        for (int i = lane; i < SS; i += 32) scnt[i] = 0;         // own the counts
        int ph = 0, s = 0;
        for (int g = 0; g < ng; g++) {
            mbar_wait_acq(sb + OFF_MBAR + s * 24, ph);           // full
            const int lb = slab[s * P + lane];
            const int bucket = lb >> 4;
            const unsigned same = __match_any_sync(0xffffffffu, bucket);
            const int pos = __popc(same & ((1u << lane) - 1u));
            const int cnt = __popc(same);
            if (lane < NCW) slcnt[s * NCW + lane] = 0;
            __syncwarp();
            slist[(s * NCW + bucket) * 32 + pos] = (uint16_t)(lb | (lane << 8));
            if (pos == 0) slcnt[s * NCW + bucket] = cnt;
            atomicAdd(&scnt[lb], 1);
            __syncwarp();
            if (lane == 0) {
                mbar_arrive(sb + OFF_MBAR + s * 24 + 8);         // ready
                mbar_arrive(sb + OFF_MBAR + s * 24 + 16);        // empty (labels done)
            }
            if (++s == NSTG) { s = 0; ph ^= 1; }
        }
    } else if (tid == NCW * 32 + 32) {
        // ---- producer thread: starts immediately after mbar-init sync ----
        int ph = 1, s = 0;
        for (int g = 0; g < ng; g++) {
            mbar_wait_rlx(sb + OFF_MBAR + s * 24 + 16, ph);      // empty
            const uint32_t ful = sb + OFF_MBAR + s * 24;
            mbar_expect_tx(ful, STAGE_TX);
            const size_t pix0 = (size_t)(base_g + g) * P;
            bulk_g2s(sb + OFF_FEAT + s * (P * CC * 4), f + pix0 * CC, P * CC * 4, ful);
            bulk_g2s(sb + OFF_LAB  + s * (P * 4),      l + pix0,      P * 4,      ful);
            if (++s == NSTG) { s = 0; ph ^= 1; }
        }
    }

    __syncthreads();

    // Flush into L2-resident final buffer via vector REDG (no DRAM scratch).
    float4* acc4 = (float4*)acc2;
    float4* gs = g_sums4 + (size_t)b * (SS * CC / 4);
    #pragma unroll
    for (int i = tid; i < SS * CC / 4; i += NTHR) redg_add_v4(&gs[i], acc4[i]);
    float* gc = g_cntg + b * SS;
    for (int i = tid; i < SS; i += NTHR) redg_add_f32(&gc[i], (float)scnt[i]);

    // Let the dependent (mean) grid launch while our REDGs drain at grid exit.
    asm volatile("griddepcontrol.launch_dependents;");
}

// Finalize: pure L2 traffic. Launched with PDL — prologue overlaps the pool
// tail; griddepcontrol.wait blocks until pool's memory flush completes
// (no-op if launched without PDL).
__global__ void __launch_bounds__(256)
mean_kernel(float4* __restrict__ out4) {
    const int i4 = blockIdx.x * 256 + threadIdx.x;      // 0 .. 32767
    const int PER_B4 = SS * CC / 4;                     // 4096
    const int b   = i4 / PER_B4;
    const int sc4 = i4 - b * PER_B4;
    const int s   = sc4 >> 4;                           // 16 float4 per segment

    asm volatile("griddepcontrol.wait;" ::: "memory");

    const float4 v = g_sums4[i4];
    const float  c = g_cntg[b * SS + s];
    const float inv = 1.0f / fmaxf(c, 1.0f);
    out4[i4] = make_float4(v.x * inv, v.y * inv, v.z * inv, v.w * inv);
    g_sums4[i4] = make_float4(0.f, 0.f, 0.f, 0.f);

    __syncthreads();   // all 16 readers of this segment's count are in this block
    if ((sc4 & 15) == 0) g_cntg[b * SS + s] = 0.0f;
}

extern "C" void kernel_launch(void* const* d_in, const int* in_sizes, int n_in,
                              void* d_out, int out_size) {
    const float* feat = (const float*)d_in[0];
    const int*   lab  = (const int*)d_in[1];
    float4*      out4 = (float4*)d_out;

    cudaFuncSetAttribute(pool_kernel,
                         cudaFuncAttributeMaxDynamicSharedMemorySize,
                         (int)SMEM_TOTAL);

    pool_kernel<<<NPART, NTHR, SMEM_TOTAL>>>(feat, lab);

    const int n4 = BB * SS * CC / 4;                    // 32768

    // PDL launch of the finalize kernel; fall back to a plain launch if the
    // attributed launch is not accepted (wait is then a no-op -> still correct).
    cudaLaunchConfig_t cfg = {};
    cfg.gridDim  = dim3(n4 / 256);
    cfg.blockDim = dim3(256);
    cudaLaunchAttribute attr[1];
    attr[0].id = cudaLaunchAttributeProgrammaticStreamSerialization;
    attr[0].val.programmaticStreamSerializationAllowed = 1;
    cfg.attrs = attr;
    cfg.numAttrs = 1;
    cudaError_t e = cudaLaunchKernelEx(&cfg, mean_kernel, out4);
    if (e != cudaSuccess) {
        mean_kernel<<<n4 / 256, 256>>>(out4);
    }
}